// round 16
// baseline (speedup 1.0000x reference)
#include <cuda_runtime.h>
#include <cuda_bf16.h>
#include <cstdint>

// ---------------------------------------------------------------- constants
#define DIM   512
#define NH    8
#define DH    64
#define NLAT  128
#define NTOK  16
#define BATCH 1024
#define MQ    (BATCH * NTOK)     // 16384 query rows
#define MKV_C 66048              // compacted K/V rows: 8 * 128*129/2
#define GRP_OFF 8256             // rows per 128-batch group
#define WSZ   (DIM * DIM)

#define KB    32                 // k-chunk
#define PADE  40                 // smem row stride in bf16 elems (80B, conflict-free)
#define BUFE  (128 * PADE)       // one buffer, elems
#define STAGE_E (4 * BUFE)       // Ah|Al|Bh|Bl, elems
#define SMEMSZ (2 * STAGE_E * 2) // bytes: 2 stages

// KV tiles: 516 bm x 8 bn; Q tiles: 128 bm x 4 bn
#define KV_TILES (516 * 8)       // 4128
#define ALL_TILES (KV_TILES + 128 * 4)   // 4640

// attention smem layout (floats)
#define APAD  68                  // K/V row stride
#define QPAD  520                 // Q row stride (full 512 cols + pad)
#define AKV   (128 * APAD)        // one K or V buffer
#define ATTN_QS   (4 * AKV)       // after ks0, vs0, ks1, vs1
#define ATTN_PS   (ATTN_QS + NTOK * QPAD)
#define ATTN_WORDS (ATTN_PS + NTOK * 129)
#define ATTN_SMEM (ATTN_WORDS * 4)   // ~181 KB

// ---------------------------------------------------------------- scratch
__device__ float g_q  [MQ    * DIM];
__device__ float g_k  [MKV_C * DIM];
__device__ float g_v  [MKV_C * DIM];

__device__ __nv_bfloat16 g_xh[MQ * DIM],    g_xl[MQ * DIM];
__device__ __nv_bfloat16 g_lh[MKV_C * DIM], g_ll[MKV_C * DIM];
__device__ __nv_bfloat16 g_ah[MQ * DIM],    g_al[MQ * DIM];
__device__ __nv_bfloat16 g_wh[4 * WSZ], g_wl[4 * WSZ]; // Wq|Wk|Wv|Wo

// ---------------------------------------------------------------- helpers
__device__ __forceinline__ uint32_t smem_u32(const void* p) {
    uint32_t a;
    asm("{ .reg .u64 t; cvta.to.shared.u64 t, %1; cvt.u32.u64 %0, t; }"
        : "=r"(a) : "l"(p));
    return a;
}

#define LDMX4(r0, r1, r2, r3, addr)                                          \
    asm volatile("ldmatrix.sync.aligned.m8n8.x4.shared.b16 {%0,%1,%2,%3}, [%4];" \
                 : "=r"(r0), "=r"(r1), "=r"(r2), "=r"(r3) : "r"(addr))

#define MMA16816(d, a, b0, b1)                                               \
    asm("mma.sync.aligned.m16n8k16.row.col.f32.bf16.bf16.f32 "               \
        "{%0,%1,%2,%3},{%4,%5,%6,%7},{%8,%9},{%0,%1,%2,%3};"                 \
        : "+f"((d)[0]), "+f"((d)[1]), "+f"((d)[2]), "+f"((d)[3])             \
        : "r"((a)[0]), "r"((a)[1]), "r"((a)[2]), "r"((a)[3]),                \
          "r"(b0), "r"(b1))

#define CP16(dst, src)                                                       \
    asm volatile("cp.async.cg.shared.global [%0], [%1], 16;"                 \
                 :: "r"(dst), "l"(src))
#define CP_COMMIT()  asm volatile("cp.async.commit_group;")
#define CP_WAIT(n)   asm volatile("cp.async.wait_group %0;" :: "n"(n))

// ---------------------------------------------------------------- hi/lo split
__device__ __forceinline__ void split2(float x, float y, uint32_t& hi, uint32_t& lo) {
    __nv_bfloat16 hx = __float2bfloat16(x), hy = __float2bfloat16(y);
    __nv_bfloat16 lx = __float2bfloat16(x - __bfloat162float(hx));
    __nv_bfloat16 ly = __float2bfloat16(y - __bfloat162float(hy));
    __nv_bfloat162 H = __halves2bfloat162(hx, hy);
    __nv_bfloat162 L = __halves2bfloat162(lx, ly);
    hi = *reinterpret_cast<uint32_t*>(&H);
    lo = *reinterpret_cast<uint32_t*>(&L);
}

__global__ __launch_bounds__(256) void conv_hilo(const float* __restrict__ src,
                                                 __nv_bfloat16* __restrict__ hi,
                                                 __nv_bfloat16* __restrict__ lo, int n4)
{
    int i = blockIdx.x * 256 + threadIdx.x;
    if (i >= n4) return;
    float4 v = ((const float4*)src)[i];
    uint2 H, L;
    split2(v.x, v.y, H.x, L.x);
    split2(v.z, v.w, H.y, L.y);
    ((uint2*)hi)[i] = H;
    ((uint2*)lo)[i] = L;
}

__global__ __launch_bounds__(256) void conv_w(const float* __restrict__ w0,
                                              const float* __restrict__ w1,
                                              const float* __restrict__ w2,
                                              const float* __restrict__ w3)
{
    int i = blockIdx.x * 256 + threadIdx.x;
    int wi = i >> 16, j = i & 65535;
    const float* src = (wi == 0) ? w0 : (wi == 1) ? w1 : (wi == 2) ? w2 : w3;
    float4 v = ((const float4*)src)[j];
    uint2 H, L;
    split2(v.x, v.y, H.x, L.x);
    split2(v.z, v.w, H.y, L.y);
    ((uint2*)(g_wh + (size_t)wi * WSZ))[j] = H;
    ((uint2*)(g_wl + (size_t)wi * WSZ))[j] = L;
}

// Dense gather: ONE block per batch element b; streams all live rows j<=m.
__global__ __launch_bounds__(256) void gather_b(const float* __restrict__ L)
{
    const int b = blockIdx.x;
    const int m = b & 127;
    const int rbase = (b >> 7) * GRP_OFF + (m * (m + 1)) / 2;
    const int total = (m + 1) * 128;          // float4s across live rows
    const float4* src = (const float4*)&L[(size_t)(b * NLAT) * DIM];

    for (int idx = threadIdx.x; idx < total; idx += 256) {
        const int j = idx >> 7;
        const int c = idx & 127;
        float4 v = src[j * 128 + c];
        uint2 H, Lo;
        split2(v.x, v.y, H.x, Lo.x);
        split2(v.z, v.w, H.y, Lo.y);
        ((uint2*)&g_lh[(size_t)(rbase + j) * DIM])[c] = H;
        ((uint2*)&g_ll[(size_t)(rbase + j) * DIM])[c] = Lo;
    }
}

// ---------------------------------------------------------------- GEMM core
struct GemmPtrs {
    const __nv_bfloat16 *Ah, *Al, *Wh, *Wl;
    const float* bias;
    float* C;
};

__device__ __forceinline__ void gemm_body(const GemmPtrs& P, int bm, int bn,
                                          __nv_bfloat16* sm)
{
    const int t = threadIdx.x;
    const int w = t >> 5, lane = t & 31;
    const int wy = w >> 2, wx = w & 3;        // warp tile (wy*64, wx*32)
    const int r8 = lane & 7, sub = lane >> 3;

    const uint32_t sbase = smem_u32(sm);

    float acc[4][4][4];
#pragma unroll
    for (int mi = 0; mi < 4; mi++)
#pragma unroll
        for (int ni = 0; ni < 4; ni++)
#pragma unroll
            for (int e = 0; e < 4; e++) acc[mi][ni][e] = 0.f;

    const int grow = t >> 1;
    const int gc   = (t & 1) * 16;
    const uint32_t soff = (uint32_t)((grow * PADE + gc) * 2);

    const int aRow = (sub & 1) * 8 + r8, aCol = (sub >> 1) * 8;
    const int bRow = (sub >> 1) * 8 + r8, bCol = (sub & 1) * 8;

    const int NCH = DIM / KB;   // 16

    const __nv_bfloat16* rowAh = &P.Ah[(size_t)(bm + grow) * DIM + gc];
    const __nv_bfloat16* rowAl = &P.Al[(size_t)(bm + grow) * DIM + gc];
    const __nv_bfloat16* rowWh = &P.Wh[(size_t)(bn + grow) * DIM + gc];
    const __nv_bfloat16* rowWl = &P.Wl[(size_t)(bn + grow) * DIM + gc];

    auto load_chunk = [&](int ch, int s) {
        const int kt = ch * KB;
        const uint32_t st = sbase + (uint32_t)(s * STAGE_E * 2);
        CP16(st + 0 * BUFE * 2 + soff,      rowAh + kt);
        CP16(st + 0 * BUFE * 2 + soff + 16, rowAh + kt + 8);
        CP16(st + 1 * BUFE * 2 + soff,      rowAl + kt);
        CP16(st + 1 * BUFE * 2 + soff + 16, rowAl + kt + 8);
        CP16(st + 2 * BUFE * 2 + soff,      rowWh + kt);
        CP16(st + 2 * BUFE * 2 + soff + 16, rowWh + kt + 8);
        CP16(st + 3 * BUFE * 2 + soff,      rowWl + kt);
        CP16(st + 3 * BUFE * 2 + soff + 16, rowWl + kt + 8);
        CP_COMMIT();
    };

    load_chunk(0, 0);

    for (int ch = 0; ch < NCH; ch++) {
        const int s = ch & 1;
        if (ch + 1 < NCH) load_chunk(ch + 1, s ^ 1);

        if (ch + 1 < NCH) CP_WAIT(1); else CP_WAIT(0);
        __syncthreads();

        const uint32_t st = sbase + (uint32_t)(s * STAGE_E * 2);
        const uint32_t aAh = st;
        const uint32_t aAl = st + 1 * BUFE * 2;
        const uint32_t aBh = st + 2 * BUFE * 2;
        const uint32_t aBl = st + 3 * BUFE * 2;

#pragma unroll
        for (int k16 = 0; k16 < KB / 16; k16++) {
            const int k0 = k16 * 16;
            uint32_t bh[8], bl[8];
#pragma unroll
            for (int p = 0; p < 2; p++) {
                const uint32_t off = (uint32_t)(((wx * 32 + p * 16 + bRow) * PADE + k0 + bCol) * 2);
                LDMX4(bh[p * 4 + 0], bh[p * 4 + 1], bh[p * 4 + 2], bh[p * 4 + 3], aBh + off);
                LDMX4(bl[p * 4 + 0], bl[p * 4 + 1], bl[p * 4 + 2], bl[p * 4 + 3], aBl + off);
            }
            uint32_t ah[4][4], al[4][4];
#pragma unroll
            for (int mi = 0; mi < 4; mi++) {
                const uint32_t off = (uint32_t)(((wy * 64 + mi * 16 + aRow) * PADE + k0 + aCol) * 2);
                LDMX4(ah[mi][0], ah[mi][1], ah[mi][2], ah[mi][3], aAh + off);
                LDMX4(al[mi][0], al[mi][1], al[mi][2], al[mi][3], aAl + off);
            }
#pragma unroll
            for (int mi = 0; mi < 4; mi++)
#pragma unroll
                for (int ni = 0; ni < 4; ni++)
                    MMA16816(acc[mi][ni], ah[mi], bh[ni * 2], bh[ni * 2 + 1]);
#pragma unroll
            for (int mi = 0; mi < 4; mi++)
#pragma unroll
                for (int ni = 0; ni < 4; ni++)
                    MMA16816(acc[mi][ni], ah[mi], bl[ni * 2], bl[ni * 2 + 1]);
#pragma unroll
            for (int mi = 0; mi < 4; mi++)
#pragma unroll
                for (int ni = 0; ni < 4; ni++)
                    MMA16816(acc[mi][ni], al[mi], bh[ni * 2], bh[ni * 2 + 1]);
        }
        __syncthreads();
    }

    const int g = lane >> 2, tg = lane & 3;
#pragma unroll
    for (int mi = 0; mi < 4; mi++) {
        const int row0 = bm + wy * 64 + mi * 16 + g;
#pragma unroll
        for (int ni = 0; ni < 4; ni++) {
            const int col = bn + wx * 32 + ni * 8 + tg * 2;
            float b0 = 0.f, b1 = 0.f;
            if (P.bias) { b0 = P.bias[col]; b1 = P.bias[col + 1]; }
            *(float2*)&P.C[(size_t)row0 * DIM + col] =
                make_float2(acc[mi][ni][0] + b0, acc[mi][ni][1] + b1);
            *(float2*)&P.C[(size_t)(row0 + 8) * DIM + col] =
                make_float2(acc[mi][ni][2] + b0, acc[mi][ni][3] + b1);
        }
    }
}

// Unified Q + K + V projection launch.
__global__ __launch_bounds__(256, 2) void gemm_all()
{
    extern __shared__ __nv_bfloat16 sm[];
    const int idx = blockIdx.x;
    GemmPtrs P;
    P.bias = nullptr;
    int bm, bn;
    if (idx < KV_TILES) {
        bm = (idx >> 3) * 128;
        const int bnv = (idx & 7) * 128;
        P.Ah = g_lh; P.Al = g_ll;
        if (bnv < 512) { P.Wh = g_wh + 1 * WSZ; P.Wl = g_wl + 1 * WSZ; P.C = g_k; bn = bnv; }
        else           { P.Wh = g_wh + 2 * WSZ; P.Wl = g_wl + 2 * WSZ; P.C = g_v; bn = bnv - 512; }
    } else {
        const int q = idx - KV_TILES;
        bm = (q >> 2) * 128;
        bn = (q & 3) * 128;
        P.Ah = g_xh; P.Al = g_xl;
        P.Wh = g_wh; P.Wl = g_wl;
        P.C = g_q;
    }
    gemm_body(P, bm, bn, sm);
}

// O projection
__global__ __launch_bounds__(256, 2) void gemm_o(const float* __restrict__ bias,
                                                 float* __restrict__ C)
{
    extern __shared__ __nv_bfloat16 sm[];
    GemmPtrs P{g_ah, g_al, g_wh + 3 * WSZ, g_wl + 3 * WSZ, bias, C};
    gemm_body(P, blockIdx.y * 128, blockIdx.x * 128, sm);
}

// ---------------------------------------------------------------- attention
// ONE block per batch element b; 256 threads; loops over 8 heads with
// double-buffered K/V cp.async pipeline. Q loaded once (16x512).
__global__ __launch_bounds__(256) void attn_kernel()
{
    extern __shared__ float smf[];
    // buffers: ks0 vs0 ks1 vs1 | qs | ps
    float* qs = smf + ATTN_QS;            // [16][QPAD]
    float* ps = smf + ATTN_PS;            // [16][129]

    const int b = blockIdx.x;
    const int t = threadIdx.x;
    const int m = b & 127;
    const int nj = m + 1;
    const size_t kvbase = (size_t)((b >> 7) * GRP_OFF + (m * (m + 1)) / 2);
    const int nf4 = nj * 16;              // float4s per head tile

    // issue K+V loads for head h into buffer s
    auto load_head = [&](int h, int s) {
        const uint32_t ka = smem_u32(smf + (2 * s) * AKV);
        const uint32_t va = smem_u32(smf + (2 * s + 1) * AKV);
        for (int idx = t; idx < nf4; idx += 256) {
            const int j = idx >> 4, c = idx & 15;
            CP16(ka + (uint32_t)((j * APAD + c * 4) * 4),
                 &g_k[(kvbase + j) * DIM + h * DH + c * 4]);
            CP16(va + (uint32_t)((j * APAD + c * 4) * 4),
                 &g_v[(kvbase + j) * DIM + h * DH + c * 4]);
        }
        CP_COMMIT();
    };

    load_head(0, 0);

    // Q tile 16x512, loaded once while head 0 flies
    for (int e = t; e < NTOK * DIM; e += 256)
        qs[(e >> 9) * QPAD + (e & 511)] =
            g_q[(size_t)(b * NTOK + (e >> 9)) * DIM + (e & 511)];

    for (int h = 0; h < NH; h++) {
        const int s = h & 1;
        if (h + 1 < NH) load_head(h + 1, s ^ 1);
        if (h + 1 < NH) CP_WAIT(1); else CP_WAIT(0);
        __syncthreads();

        const float* ks = smf + (2 * s) * AKV;
        const float* vs = smf + (2 * s + 1) * AKV;

        // ---- scores: one K row per thread (t < nj) ----
        if (t < nj) {
            float sc[NTOK];
#pragma unroll
            for (int i = 0; i < NTOK; i++) sc[i] = 0.f;
#pragma unroll
            for (int c = 0; c < 16; c++) {
                float4 kk = *(const float4*)&ks[t * APAD + c * 4];
#pragma unroll
                for (int i = 0; i < NTOK; i++) {
                    float4 qq = *(const float4*)&qs[i * QPAD + h * DH + c * 4];
                    sc[i] += qq.x * kk.x + qq.y * kk.y + qq.z * kk.z + qq.w * kk.w;
                }
            }
#pragma unroll
            for (int i = 0; i < NTOK; i++) ps[i * 129 + t] = sc[i] * 0.125f;
        }
        __syncthreads();

        // ---- softmax: threads 0..127, 8 per row, shuffle reduction ----
        if (t < 128) {
            const int row = t >> 3;
            const int sub = t & 7;
            float pm = -1e30f;
            for (int j = sub; j < nj; j += 8) pm = fmaxf(pm, ps[row * 129 + j]);
#pragma unroll
            for (int o = 1; o < 8; o <<= 1)
                pm = fmaxf(pm, __shfl_xor_sync(0xFFFFFFFFu, pm, o));
            float psum = 0.f;
            for (int j = sub; j < nj; j += 8) {
                float e = expf(ps[row * 129 + j] - pm);
                ps[row * 129 + j] = e;
                psum += e;
            }
#pragma unroll
            for (int o = 1; o < 8; o <<= 1)
                psum += __shfl_xor_sync(0xFFFFFFFFu, psum, o);
            const float inv = 1.f / psum;
            for (int j = sub; j < nj; j += 8) ps[row * 129 + j] *= inv;
        }
        __syncthreads();

        // ---- P @ V: 256 threads, d = t&63, 4 rows each ----
        {
            const int d  = t & 63;
            const int i0 = t >> 6;        // 0..3
            float acc[4] = {0.f, 0.f, 0.f, 0.f};
            for (int j = 0; j < nj; j++) {
                float vv = vs[j * APAD + d];
#pragma unroll
                for (int ii = 0; ii < 4; ii++)
                    acc[ii] += ps[(i0 + 4 * ii) * 129 + j] * vv;
            }
#pragma unroll
            for (int ii = 0; ii < 4; ii++) {
                const int i = i0 + 4 * ii;
                size_t idx = (size_t)(b * NTOK + i) * DIM + h * DH + d;
                __nv_bfloat16 hv = __float2bfloat16(acc[ii]);
                g_ah[idx] = hv;
                g_al[idx] = __float2bfloat16(acc[ii] - __bfloat162float(hv));
            }
        }
        __syncthreads();
    }
}

// ---------------------------------------------------------------- launch
extern "C" void kernel_launch(void* const* d_in, const int* in_sizes, int n_in,
                              void* d_out, int out_size)
{
    const float* x  = (const float*)d_in[0];
    const float* l  = (const float*)d_in[1];
    const float* Wq = (const float*)d_in[2];
    const float* Wk = (const float*)d_in[3];
    const float* Wv = (const float*)d_in[4];
    const float* Wo = (const float*)d_in[5];
    const float* bo = (const float*)d_in[6];
    float* out = (float*)d_out;

    __nv_bfloat16 *pxh, *pxl;
    cudaGetSymbolAddress((void**)&pxh, g_xh);
    cudaGetSymbolAddress((void**)&pxl, g_xl);

    cudaFuncSetAttribute(gemm_all, cudaFuncAttributeMaxDynamicSharedMemorySize, SMEMSZ);
    cudaFuncSetAttribute(gemm_o,   cudaFuncAttributeMaxDynamicSharedMemorySize, SMEMSZ);
    cudaFuncSetAttribute(attn_kernel, cudaFuncAttributeMaxDynamicSharedMemorySize, ATTN_SMEM);

    conv_hilo<<<(MQ * DIM / 4 + 255) / 256, 256>>>(x, pxh, pxl, MQ * DIM / 4);
    conv_w<<<4 * WSZ / 4 / 256, 256>>>(Wq, Wk, Wv, Wo);
    gather_b<<<BATCH, 256>>>(l);

    gemm_all<<<ALL_TILES, 256, SMEMSZ>>>();
    attn_kernel<<<BATCH, 256, ATTN_SMEM>>>();
    gemm_o<<<dim3(4, MQ / 128), 256, SMEMSZ>>>(bo, out);
}

// round 17
// speedup vs baseline: 1.1994x; 1.1994x over previous
#include <cuda_runtime.h>
#include <cuda_bf16.h>
#include <cstdint>

// ---------------------------------------------------------------- constants
#define DIM   512
#define NH    8
#define DH    64
#define NLAT  128
#define NTOK  16
#define BATCH 1024
#define MQ    (BATCH * NTOK)     // 16384 query rows
#define MKV_C 66048              // compacted K/V rows: 8 * 128*129/2
#define GRP_OFF 8256             // rows per 128-batch group
#define WSZ   (DIM * DIM)

#define KB    32                 // k-chunk
#define PADE  40                 // smem row stride in bf16 elems (80B, conflict-free)
#define BUFE  (128 * PADE)       // one buffer, elems
#define STAGE_E (4 * BUFE)       // Ah|Al|Bh|Bl, elems
#define SMEMSZ (2 * STAGE_E * 2) // bytes: 2 stages

// KV tiles: 516 bm x 8 bn; Q tiles: 128 bm x 4 bn
#define KV_TILES (516 * 8)       // 4128
#define ALL_TILES (KV_TILES + 128 * 4)   // 4640

// attention smem layout (floats) — single K/V buffer (reused), 4 CTAs/SM
#define APAD  68
#define QPAD  68
#define ATTN_KV   0                          // [128][APAD] K then V (reused)
#define ATTN_QS   (128 * APAD)
#define ATTN_PS   (ATTN_QS + NTOK * QPAD)
#define ATTN_WORDS (ATTN_PS + NTOK * 129)
#define ATTN_SMEM (ATTN_WORDS * 4)           // ~47.5 KB

// ---------------------------------------------------------------- scratch
__device__ float g_q  [MQ    * DIM];
__device__ float g_k  [MKV_C * DIM];
__device__ float g_v  [MKV_C * DIM];

__device__ __nv_bfloat16 g_xh[MQ * DIM],    g_xl[MQ * DIM];
__device__ __nv_bfloat16 g_lh[MKV_C * DIM], g_ll[MKV_C * DIM];
__device__ __nv_bfloat16 g_ah[MQ * DIM],    g_al[MQ * DIM];
__device__ __nv_bfloat16 g_wh[4 * WSZ], g_wl[4 * WSZ]; // Wq|Wk|Wv|Wo

// ---------------------------------------------------------------- helpers
__device__ __forceinline__ uint32_t smem_u32(const void* p) {
    uint32_t a;
    asm("{ .reg .u64 t; cvta.to.shared.u64 t, %1; cvt.u32.u64 %0, t; }"
        : "=r"(a) : "l"(p));
    return a;
}

#define LDMX4(r0, r1, r2, r3, addr)                                          \
    asm volatile("ldmatrix.sync.aligned.m8n8.x4.shared.b16 {%0,%1,%2,%3}, [%4];" \
                 : "=r"(r0), "=r"(r1), "=r"(r2), "=r"(r3) : "r"(addr))

#define MMA16816(d, a, b0, b1)                                               \
    asm("mma.sync.aligned.m16n8k16.row.col.f32.bf16.bf16.f32 "               \
        "{%0,%1,%2,%3},{%4,%5,%6,%7},{%8,%9},{%0,%1,%2,%3};"                 \
        : "+f"((d)[0]), "+f"((d)[1]), "+f"((d)[2]), "+f"((d)[3])             \
        : "r"((a)[0]), "r"((a)[1]), "r"((a)[2]), "r"((a)[3]),                \
          "r"(b0), "r"(b1))

#define CP16(dst, src)                                                       \
    asm volatile("cp.async.cg.shared.global [%0], [%1], 16;"                 \
                 :: "r"(dst), "l"(src))
#define CP_COMMIT()  asm volatile("cp.async.commit_group;")
#define CP_WAIT(n)   asm volatile("cp.async.wait_group %0;" :: "n"(n))

// ---------------------------------------------------------------- hi/lo split
__device__ __forceinline__ void split2(float x, float y, uint32_t& hi, uint32_t& lo) {
    __nv_bfloat16 hx = __float2bfloat16(x), hy = __float2bfloat16(y);
    __nv_bfloat16 lx = __float2bfloat16(x - __bfloat162float(hx));
    __nv_bfloat16 ly = __float2bfloat16(y - __bfloat162float(hy));
    __nv_bfloat162 H = __halves2bfloat162(hx, hy);
    __nv_bfloat162 L = __halves2bfloat162(lx, ly);
    hi = *reinterpret_cast<uint32_t*>(&H);
    lo = *reinterpret_cast<uint32_t*>(&L);
}

__global__ __launch_bounds__(256) void conv_hilo(const float* __restrict__ src,
                                                 __nv_bfloat16* __restrict__ hi,
                                                 __nv_bfloat16* __restrict__ lo, int n4)
{
    int i = blockIdx.x * 256 + threadIdx.x;
    if (i >= n4) return;
    float4 v = ((const float4*)src)[i];
    uint2 H, L;
    split2(v.x, v.y, H.x, L.x);
    split2(v.z, v.w, H.y, L.y);
    ((uint2*)hi)[i] = H;
    ((uint2*)lo)[i] = L;
}

__global__ __launch_bounds__(256) void conv_w(const float* __restrict__ w0,
                                              const float* __restrict__ w1,
                                              const float* __restrict__ w2,
                                              const float* __restrict__ w3)
{
    int i = blockIdx.x * 256 + threadIdx.x;
    int wi = i >> 16, j = i & 65535;
    const float* src = (wi == 0) ? w0 : (wi == 1) ? w1 : (wi == 2) ? w2 : w3;
    float4 v = ((const float4*)src)[j];
    uint2 H, L;
    split2(v.x, v.y, H.x, L.x);
    split2(v.z, v.w, H.y, L.y);
    ((uint2*)(g_wh + (size_t)wi * WSZ))[j] = H;
    ((uint2*)(g_wl + (size_t)wi * WSZ))[j] = L;
}

// Dense gather: ONE block per batch element b; streams all live rows j<=m.
__global__ __launch_bounds__(256) void gather_b(const float* __restrict__ L)
{
    const int b = blockIdx.x;
    const int m = b & 127;
    const int rbase = (b >> 7) * GRP_OFF + (m * (m + 1)) / 2;
    const int total = (m + 1) * 128;          // float4s across live rows
    const float4* src = (const float4*)&L[(size_t)(b * NLAT) * DIM];

    for (int idx = threadIdx.x; idx < total; idx += 256) {
        const int j = idx >> 7;
        const int c = idx & 127;
        float4 v = src[j * 128 + c];
        uint2 H, Lo;
        split2(v.x, v.y, H.x, Lo.x);
        split2(v.z, v.w, H.y, Lo.y);
        ((uint2*)&g_lh[(size_t)(rbase + j) * DIM])[c] = H;
        ((uint2*)&g_ll[(size_t)(rbase + j) * DIM])[c] = Lo;
    }
}

// ---------------------------------------------------------------- GEMM core
struct GemmPtrs {
    const __nv_bfloat16 *Ah, *Al, *Wh, *Wl;
    const float* bias;
    float* C;
};

__device__ __forceinline__ void gemm_body(const GemmPtrs& P, int bm, int bn,
                                          __nv_bfloat16* sm)
{
    const int t = threadIdx.x;
    const int w = t >> 5, lane = t & 31;
    const int wy = w >> 2, wx = w & 3;        // warp tile (wy*64, wx*32)
    const int r8 = lane & 7, sub = lane >> 3;

    const uint32_t sbase = smem_u32(sm);

    float acc[4][4][4];
#pragma unroll
    for (int mi = 0; mi < 4; mi++)
#pragma unroll
        for (int ni = 0; ni < 4; ni++)
#pragma unroll
            for (int e = 0; e < 4; e++) acc[mi][ni][e] = 0.f;

    const int grow = t >> 1;
    const int gc   = (t & 1) * 16;
    const uint32_t soff = (uint32_t)((grow * PADE + gc) * 2);

    const int aRow = (sub & 1) * 8 + r8, aCol = (sub >> 1) * 8;
    const int bRow = (sub >> 1) * 8 + r8, bCol = (sub & 1) * 8;

    const int NCH = DIM / KB;   // 16

    const __nv_bfloat16* rowAh = &P.Ah[(size_t)(bm + grow) * DIM + gc];
    const __nv_bfloat16* rowAl = &P.Al[(size_t)(bm + grow) * DIM + gc];
    const __nv_bfloat16* rowWh = &P.Wh[(size_t)(bn + grow) * DIM + gc];
    const __nv_bfloat16* rowWl = &P.Wl[(size_t)(bn + grow) * DIM + gc];

    auto load_chunk = [&](int ch, int s) {
        const int kt = ch * KB;
        const uint32_t st = sbase + (uint32_t)(s * STAGE_E * 2);
        CP16(st + 0 * BUFE * 2 + soff,      rowAh + kt);
        CP16(st + 0 * BUFE * 2 + soff + 16, rowAh + kt + 8);
        CP16(st + 1 * BUFE * 2 + soff,      rowAl + kt);
        CP16(st + 1 * BUFE * 2 + soff + 16, rowAl + kt + 8);
        CP16(st + 2 * BUFE * 2 + soff,      rowWh + kt);
        CP16(st + 2 * BUFE * 2 + soff + 16, rowWh + kt + 8);
        CP16(st + 3 * BUFE * 2 + soff,      rowWl + kt);
        CP16(st + 3 * BUFE * 2 + soff + 16, rowWl + kt + 8);
        CP_COMMIT();
    };

    load_chunk(0, 0);

    for (int ch = 0; ch < NCH; ch++) {
        const int s = ch & 1;
        if (ch + 1 < NCH) load_chunk(ch + 1, s ^ 1);

        if (ch + 1 < NCH) CP_WAIT(1); else CP_WAIT(0);
        __syncthreads();

        const uint32_t st = sbase + (uint32_t)(s * STAGE_E * 2);
        const uint32_t aAh = st;
        const uint32_t aAl = st + 1 * BUFE * 2;
        const uint32_t aBh = st + 2 * BUFE * 2;
        const uint32_t aBl = st + 3 * BUFE * 2;

#pragma unroll
        for (int k16 = 0; k16 < KB / 16; k16++) {
            const int k0 = k16 * 16;
            uint32_t bh[8], bl[8];
#pragma unroll
            for (int p = 0; p < 2; p++) {
                const uint32_t off = (uint32_t)(((wx * 32 + p * 16 + bRow) * PADE + k0 + bCol) * 2);
                LDMX4(bh[p * 4 + 0], bh[p * 4 + 1], bh[p * 4 + 2], bh[p * 4 + 3], aBh + off);
                LDMX4(bl[p * 4 + 0], bl[p * 4 + 1], bl[p * 4 + 2], bl[p * 4 + 3], aBl + off);
            }
            uint32_t ah[4][4], al[4][4];
#pragma unroll
            for (int mi = 0; mi < 4; mi++) {
                const uint32_t off = (uint32_t)(((wy * 64 + mi * 16 + aRow) * PADE + k0 + aCol) * 2);
                LDMX4(ah[mi][0], ah[mi][1], ah[mi][2], ah[mi][3], aAh + off);
                LDMX4(al[mi][0], al[mi][1], al[mi][2], al[mi][3], aAl + off);
            }
#pragma unroll
            for (int mi = 0; mi < 4; mi++)
#pragma unroll
                for (int ni = 0; ni < 4; ni++)
                    MMA16816(acc[mi][ni], ah[mi], bh[ni * 2], bh[ni * 2 + 1]);
#pragma unroll
            for (int mi = 0; mi < 4; mi++)
#pragma unroll
                for (int ni = 0; ni < 4; ni++)
                    MMA16816(acc[mi][ni], ah[mi], bl[ni * 2], bl[ni * 2 + 1]);
#pragma unroll
            for (int mi = 0; mi < 4; mi++)
#pragma unroll
                for (int ni = 0; ni < 4; ni++)
                    MMA16816(acc[mi][ni], al[mi], bh[ni * 2], bh[ni * 2 + 1]);
        }
        __syncthreads();
    }

    const int g = lane >> 2, tg = lane & 3;
#pragma unroll
    for (int mi = 0; mi < 4; mi++) {
        const int row0 = bm + wy * 64 + mi * 16 + g;
#pragma unroll
        for (int ni = 0; ni < 4; ni++) {
            const int col = bn + wx * 32 + ni * 8 + tg * 2;
            float b0 = 0.f, b1 = 0.f;
            if (P.bias) { b0 = P.bias[col]; b1 = P.bias[col + 1]; }
            *(float2*)&P.C[(size_t)row0 * DIM + col] =
                make_float2(acc[mi][ni][0] + b0, acc[mi][ni][1] + b1);
            *(float2*)&P.C[(size_t)(row0 + 8) * DIM + col] =
                make_float2(acc[mi][ni][2] + b0, acc[mi][ni][3] + b1);
        }
    }
}

// Unified Q + K + V projection launch.
__global__ __launch_bounds__(256, 2) void gemm_all()
{
    extern __shared__ __nv_bfloat16 sm[];
    const int idx = blockIdx.x;
    GemmPtrs P;
    P.bias = nullptr;
    int bm, bn;
    if (idx < KV_TILES) {
        bm = (idx >> 3) * 128;
        const int bnv = (idx & 7) * 128;
        P.Ah = g_lh; P.Al = g_ll;
        if (bnv < 512) { P.Wh = g_wh + 1 * WSZ; P.Wl = g_wl + 1 * WSZ; P.C = g_k; bn = bnv; }
        else           { P.Wh = g_wh + 2 * WSZ; P.Wl = g_wl + 2 * WSZ; P.C = g_v; bn = bnv - 512; }
    } else {
        const int q = idx - KV_TILES;
        bm = (q >> 2) * 128;
        bn = (q & 3) * 128;
        P.Ah = g_xh; P.Al = g_xl;
        P.Wh = g_wh; P.Wl = g_wl;
        P.C = g_q;
    }
    gemm_body(P, bm, bn, sm);
}

// O projection
__global__ __launch_bounds__(256, 2) void gemm_o(const float* __restrict__ bias,
                                                 float* __restrict__ C)
{
    extern __shared__ __nv_bfloat16 sm[];
    GemmPtrs P{g_ah, g_al, g_wh + 3 * WSZ, g_wl + 3 * WSZ, bias, C};
    gemm_body(P, blockIdx.y * 128, blockIdx.x * 128, sm);
}

// ---------------------------------------------------------------- attention
// One block per (b,h); 128 threads; SINGLE K/V smem buffer (reused) so
// 4 CTAs/SM co-reside. V load overlaps softmax.
__global__ __launch_bounds__(128) void attn_kernel()
{
    extern __shared__ float smf[];
    float* kv = smf + ATTN_KV;     // [128][APAD] — K, then reused for V
    float* qs = smf + ATTN_QS;     // [16][QPAD]
    float* ps = smf + ATTN_PS;     // [16][129]

    const int b = blockIdx.x;
    const int h = blockIdx.y;
    const int t = threadIdx.x;
    const int m = b & 127;
    const int nj = m + 1;
    const size_t kvbase = (size_t)((b >> 7) * GRP_OFF + (m * (m + 1)) / 2);

    const uint32_t kva = smem_u32(kv);
    const int nf4 = nj * 16;

    // issue K burst
    for (int idx = t; idx < nf4; idx += 128) {
        const int j = idx >> 4, c = idx & 15;
        CP16(kva + (uint32_t)((j * APAD + c * 4) * 4),
             &g_k[(kvbase + j) * DIM + h * DH + c * 4]);
    }
    CP_COMMIT();

    // load Q tile while K flies
#pragma unroll
    for (int u = 0; u < 8; u++) {
        int e = t + u * 128;
        qs[(e >> 6) * QPAD + (e & 63)] =
            g_q[(size_t)(b * NTOK + (e >> 6)) * DIM + h * DH + (e & 63)];
    }

    CP_WAIT(0);
    __syncthreads();

    // ---- scores: one K row per thread, from smem ----
    if (t < nj) {
        float s[NTOK];
#pragma unroll
        for (int i = 0; i < NTOK; i++) s[i] = 0.f;
#pragma unroll
        for (int c = 0; c < 16; c++) {
            float4 kk = *(const float4*)&kv[t * APAD + c * 4];
#pragma unroll
            for (int i = 0; i < NTOK; i++) {
                float4 qq = *(const float4*)&qs[i * QPAD + c * 4];  // broadcast
                s[i] += qq.x * kk.x + qq.y * kk.y + qq.z * kk.z + qq.w * kk.w;
            }
        }
#pragma unroll
        for (int i = 0; i < NTOK; i++) ps[i * 129 + t] = s[i] * 0.125f;
    }
    __syncthreads();   // all K reads done; buffer free for V

    // issue V burst into the SAME buffer (overlaps softmax)
    for (int idx = t; idx < nf4; idx += 128) {
        const int j = idx >> 4, c = idx & 15;
        CP16(kva + (uint32_t)((j * APAD + c * 4) * 4),
             &g_v[(kvbase + j) * DIM + h * DH + c * 4]);
    }
    CP_COMMIT();

    // ---- softmax: 8 threads per row, shuffle reduction ----
    {
        const int row = t >> 3;
        const int sub = t & 7;
        float pm = -1e30f;
        for (int j = sub; j < nj; j += 8) pm = fmaxf(pm, ps[row * 129 + j]);
#pragma unroll
        for (int o = 1; o < 8; o <<= 1)
            pm = fmaxf(pm, __shfl_xor_sync(0xFFFFFFFFu, pm, o));
        float psum = 0.f;
        for (int j = sub; j < nj; j += 8) {
            float e = expf(ps[row * 129 + j] - pm);
            ps[row * 129 + j] = e;
            psum += e;
        }
#pragma unroll
        for (int o = 1; o < 8; o <<= 1)
            psum += __shfl_xor_sync(0xFFFFFFFFu, psum, o);
        const float inv = 1.f / psum;
        for (int j = sub; j < nj; j += 8) ps[row * 129 + j] *= inv;
    }

    CP_WAIT(0);        // V ready
    __syncthreads();

    // ---- P @ V from smem ----
    {
        const int d  = t & 63;
        const int i0 = t >> 6;
        float acc[8];
#pragma unroll
        for (int ii = 0; ii < 8; ii++) acc[ii] = 0.f;
        for (int j = 0; j < nj; j++) {
            float vv = kv[j * APAD + d];
#pragma unroll
            for (int ii = 0; ii < 8; ii++)
                acc[ii] += ps[(i0 + 2 * ii) * 129 + j] * vv;
        }
#pragma unroll
        for (int ii = 0; ii < 8; ii++) {
            size_t idx = (size_t)(b * NTOK + i0 + 2 * ii) * DIM + h * DH + d;
            __nv_bfloat16 hv = __float2bfloat16(acc[ii]);
            g_ah[idx] = hv;
            g_al[idx] = __float2bfloat16(acc[ii] - __bfloat162float(hv));
        }
    }
}

// ---------------------------------------------------------------- launch
extern "C" void kernel_launch(void* const* d_in, const int* in_sizes, int n_in,
                              void* d_out, int out_size)
{
    const float* x  = (const float*)d_in[0];
    const float* l  = (const float*)d_in[1];
    const float* Wq = (const float*)d_in[2];
    const float* Wk = (const float*)d_in[3];
    const float* Wv = (const float*)d_in[4];
    const float* Wo = (const float*)d_in[5];
    const float* bo = (const float*)d_in[6];
    float* out = (float*)d_out;

    __nv_bfloat16 *pxh, *pxl;
    cudaGetSymbolAddress((void**)&pxh, g_xh);
    cudaGetSymbolAddress((void**)&pxl, g_xl);

    cudaFuncSetAttribute(gemm_all, cudaFuncAttributeMaxDynamicSharedMemorySize, SMEMSZ);
    cudaFuncSetAttribute(gemm_o,   cudaFuncAttributeMaxDynamicSharedMemorySize, SMEMSZ);
    cudaFuncSetAttribute(attn_kernel, cudaFuncAttributeMaxDynamicSharedMemorySize, ATTN_SMEM);

    conv_hilo<<<(MQ * DIM / 4 + 255) / 256, 256>>>(x, pxh, pxl, MQ * DIM / 4);
    conv_w<<<4 * WSZ / 4 / 256, 256>>>(Wq, Wk, Wv, Wo);
    gather_b<<<BATCH, 256>>>(l);

    gemm_all<<<ALL_TILES, 256, SMEMSZ>>>();
    attn_kernel<<<dim3(BATCH, NH), 128, ATTN_SMEM>>>();
    gemm_o<<<dim3(4, MQ / 128), 256, SMEMSZ>>>(bo, out);
}